// round 2
// baseline (speedup 1.0000x reference)
#include <cuda_runtime.h>
#include <cuda_bf16.h>
#include <math.h>

// Problem constants (fixed by the dataset)
#define BATCH 16
#define SEQ   4096
#define DIM   1152
#define OUTL  1024
#define DIM4  (DIM / 4)        // 288 float4 per row
#define POOLED_ELEMS ((size_t)BATCH * OUTL * DIM)   // 18,874,368

// scale = sqrt(1152) / k^2 = sqrt(1152) / 4
#define POOL_SCALE 8.4852813742385702928f

// Scratch (device globals — no allocation allowed in kernel_launch)
__device__ int g_cnt [BATCH * OUTL];   // TOTAL tokens per (batch, cell)  -> mask
__device__ int g_vcnt[BATCH * OUTL];   // NON-PADDED tokens per cell      -> loop bound
__device__ int g_off [BATCH * OUTL];   // exclusive offsets within batch
__device__ int g_list[BATCH * SEQ];    // non-padded token ids, CSR order per batch

// ---------------------------------------------------------------------------
// Kernel 1: per-batch  max_x -> divk, bucket counts (total + valid),
//           block scan, CSR fill with only non-padded tokens.
// grid = BATCH, block = 1024. Each thread handles 4 tokens (strided).
// ---------------------------------------------------------------------------
__global__ __launch_bounds__(1024, 1)
void build_kernel(const int2* __restrict__ pos,
                  const unsigned char* __restrict__ pad)
{
    __shared__ int sTot[OUTL];   // total counts (mask)
    __shared__ int sVal[OUTL];   // valid counts (scan + cursors)
    __shared__ int sWarp[32];

    const int b    = blockIdx.x;
    const int t    = threadIdx.x;
    const int lane = t & 31;
    const int wid  = t >> 5;

    const int2* p = pos + (size_t)b * SEQ;

    // Load this thread's 4 tokens' (x, y) and pad flags; track clamped max x.
    int2 v[4];
    unsigned char pd[4];
    int mymax = 0;
#pragma unroll
    for (int j = 0; j < 4; j++) {
        v[j]  = p[t + j * 1024];
        pd[j] = (pad != nullptr) ? pad[(size_t)b * SEQ + t + j * 1024] : 0;
        mymax = max(mymax, max(v[j].x, 0));
    }

    // Block max-reduce -> sWarp[0]
#pragma unroll
    for (int o = 16; o > 0; o >>= 1)
        mymax = max(mymax, __shfl_down_sync(0xffffffffu, mymax, o));
    if (lane == 0) sWarp[wid] = mymax;
    __syncthreads();
    if (wid == 0) {
        int m = sWarp[lane];
#pragma unroll
        for (int o = 16; o > 0; o >>= 1)
            m = max(m, __shfl_down_sync(0xffffffffu, m, o));
        if (lane == 0) sWarp[0] = m;
    }
    __syncthreads();
    const int divk = (sWarp[0] + 1) >> 1;   // (max_x + 1) // k, k = 2
    __syncthreads();                        // everyone has divk before sWarp reuse

    // Phase 1: bucket counts in SMEM (total for mask, valid for list)
    sTot[t] = 0;
    sVal[t] = 0;
    __syncthreads();

    int idxv[4];
#pragma unroll
    for (int j = 0; j < 4; j++) {
        const int px = max(v[j].x, 0);
        const int py = max(v[j].y, 0);
        int id = (px >> 1) + divk * (py >> 1);
        if (id < 0 || id >= OUTL) id = -1;  // JAX drops OOB scatter indices
        idxv[j] = id;
        if (id >= 0) {
            atomicAdd(&sTot[id], 1);
            if (!pd[j]) atomicAdd(&sVal[id], 1);
        }
    }
    __syncthreads();

    // Phase 2: block exclusive scan of the 1024 VALID counts
    const int tot = sTot[t];
    const int cnt = sVal[t];
    int inc = cnt;
#pragma unroll
    for (int o = 1; o < 32; o <<= 1) {
        int n = __shfl_up_sync(0xffffffffu, inc, o);
        if (lane >= o) inc += n;
    }
    if (lane == 31) sWarp[wid] = inc;
    __syncthreads();
    if (wid == 0) {
        const int wv = sWarp[lane];
        int winc = wv;
#pragma unroll
        for (int o = 1; o < 32; o <<= 1) {
            int n = __shfl_up_sync(0xffffffffu, winc, o);
            if (lane >= o) winc += n;
        }
        sWarp[lane] = winc - wv;            // exclusive prefix of warp sums
    }
    __syncthreads();
    const int excl = inc - cnt + sWarp[wid];

    g_cnt [b * OUTL + t] = tot;
    g_vcnt[b * OUTL + t] = cnt;
    g_off [b * OUTL + t] = excl;

    // Phase 3: reuse sVal as per-cell cursors, fill CSR list (non-padded only)
    __syncthreads();
    sVal[t] = excl;
    __syncthreads();
#pragma unroll
    for (int j = 0; j < 4; j++) {
        if (idxv[j] >= 0 && !pd[j]) {
            const int slot = atomicAdd(&sVal[idxv[j]], 1);
            g_list[b * SEQ + slot] = t + j * 1024;
        }
    }
}

// ---------------------------------------------------------------------------
// Kernel 2: gather-pool. One block per output row, one float4 per thread.
// grid = BATCH*OUTL = 16384, block = DIM4 = 288 (9 warps).
// Chunked prefetch of up to 8 token ids -> 8 independent row loads in flight.
// ---------------------------------------------------------------------------
#define CHUNK 8

__global__ __launch_bounds__(DIM4)
void pool_kernel(const float4* __restrict__ hidden,
                 float4* __restrict__ out,
                 float* __restrict__ maskF,
                 unsigned char* __restrict__ maskB)
{
    const int bid = blockIdx.x;        // b*OUTL + cell
    const int b   = bid >> 10;
    const int t   = threadIdx.x;       // 0..287

    const int vcnt = g_vcnt[bid];
    const int base = g_off[bid] + b * SEQ;

    float4 acc = make_float4(0.f, 0.f, 0.f, 0.f);

    for (int i = 0; i < vcnt; i += CHUNK) {
        const int m = min(vcnt - i, CHUNK);

        // Batch the index loads: independent, MLP = m
        int sv[CHUNK];
#pragma unroll
        for (int j = 0; j < CHUNK; j++)
            if (j < m) sv[j] = g_list[base + i + j];

        // Row loads: all m issued back-to-back, independent
        float4 hv[CHUNK];
#pragma unroll
        for (int j = 0; j < CHUNK; j++)
            if (j < m) hv[j] = hidden[(size_t)((b << 12) + sv[j]) * DIM4 + t];

#pragma unroll
        for (int j = 0; j < CHUNK; j++)
            if (j < m) {
                acc.x += hv[j].x; acc.y += hv[j].y;
                acc.z += hv[j].z; acc.w += hv[j].w;
            }
    }

    acc.x *= POOL_SCALE; acc.y *= POOL_SCALE;
    acc.z *= POOL_SCALE; acc.w *= POOL_SCALE;

    out[(size_t)bid * DIM4 + t] = acc;

    if (t == 0) {
        const bool mk = (g_cnt[bid] > 0);
        if (maskF) maskF[bid] = mk ? 1.0f : 0.0f;
        if (maskB) maskB[bid] = mk ? 1 : 0;
    }
}

// ---------------------------------------------------------------------------
extern "C" void kernel_launch(void* const* d_in, const int* in_sizes, int n_in,
                              void* d_out, int out_size)
{
    // Classify inputs by element count (robust to optional scalar output_length)
    const float*         hidden = nullptr;
    const int2*          pos    = nullptr;
    const unsigned char* pad    = nullptr;

    for (int i = 0; i < n_in; i++) {
        const long long sz = in_sizes[i];
        if (sz == (long long)BATCH * SEQ * DIM)      hidden = (const float*)d_in[i];
        else if (sz == (long long)BATCH * SEQ * 2)   pos    = (const int2*)d_in[i];
        else if (sz == (long long)BATCH * SEQ)       pad    = (const unsigned char*)d_in[i];
        // size-1 scalar (output_length) ignored — shapes are compile-time fixed
    }

    float* out = (float*)d_out;

    // Mask layout detection from out_size (elements of output dtype)
    float*         maskF = nullptr;
    unsigned char* maskB = nullptr;
    const long long extra = (long long)out_size - (long long)POOLED_ELEMS;
    if (extra == (long long)BATCH * OUTL) {
        maskF = out + POOLED_ELEMS;                       // mask as float32
    } else if (extra == (long long)BATCH * OUTL / 4) {
        maskB = (unsigned char*)(out + POOLED_ELEMS);     // mask as packed bytes
    }

    build_kernel<<<BATCH, 1024>>>(pos, pad);
    pool_kernel<<<BATCH * OUTL, DIM4>>>((const float4*)hidden,
                                        (float4*)out, maskF, maskB);
}

// round 3
// speedup vs baseline: 1.5472x; 1.5472x over previous
#include <cuda_runtime.h>
#include <cuda_bf16.h>
#include <math.h>

// Problem constants (fixed by the dataset)
#define BATCH 16
#define SEQ   4096
#define DIM   1152
#define OUTL  1024
#define DIM4  (DIM / 4)        // 288 float4 per row
#define POOLED_ELEMS ((size_t)BATCH * OUTL * DIM)   // 18,874,368

// scale = sqrt(1152) / k^2 = sqrt(1152) / 4
#define POOL_SCALE 8.4852813742385702928f

// Scratch (device globals — no allocation allowed in kernel_launch)
__device__ int g_cnt [BATCH * OUTL];   // TOTAL tokens per (batch, cell)  -> mask
__device__ int g_vcnt[BATCH * OUTL];   // NON-PADDED tokens per cell      -> loop bound
__device__ int g_off [BATCH * OUTL];   // exclusive offsets within batch
__device__ int g_list[BATCH * SEQ];    // non-padded token ids, CSR order per batch

// ---------------------------------------------------------------------------
// Kernel 1: per-batch  max_x -> divk, bucket counts (total + valid),
//           block scan, CSR fill with only non-padded tokens.
// grid = BATCH, block = 1024. Each thread handles 4 tokens (strided).
// ---------------------------------------------------------------------------
__global__ __launch_bounds__(1024, 1)
void build_kernel(const int2* __restrict__ pos,
                  const unsigned char* __restrict__ pad)
{
    __shared__ int sTot[OUTL];   // total counts (mask)
    __shared__ int sVal[OUTL];   // valid counts (scan + cursors)
    __shared__ int sWarp[32];

    const int b    = blockIdx.x;
    const int t    = threadIdx.x;
    const int lane = t & 31;
    const int wid  = t >> 5;

    const int2* p = pos + (size_t)b * SEQ;

    // Load this thread's 4 tokens' (x, y) and pad flags; track clamped max x.
    int2 v[4];
    unsigned char pd[4];
    int mymax = 0;
#pragma unroll
    for (int j = 0; j < 4; j++) {
        v[j]  = p[t + j * 1024];
        pd[j] = (pad != nullptr) ? pad[(size_t)b * SEQ + t + j * 1024] : 0;
        mymax = max(mymax, max(v[j].x, 0));
    }

    // Block max-reduce -> sWarp[0]
#pragma unroll
    for (int o = 16; o > 0; o >>= 1)
        mymax = max(mymax, __shfl_down_sync(0xffffffffu, mymax, o));
    if (lane == 0) sWarp[wid] = mymax;
    __syncthreads();
    if (wid == 0) {
        int m = sWarp[lane];
#pragma unroll
        for (int o = 16; o > 0; o >>= 1)
            m = max(m, __shfl_down_sync(0xffffffffu, m, o));
        if (lane == 0) sWarp[0] = m;
    }
    __syncthreads();
    const int divk = (sWarp[0] + 1) >> 1;   // (max_x + 1) // k, k = 2
    __syncthreads();                        // everyone has divk before sWarp reuse

    // Phase 1: bucket counts in SMEM (total for mask, valid for list)
    sTot[t] = 0;
    sVal[t] = 0;
    __syncthreads();

    int idxv[4];
#pragma unroll
    for (int j = 0; j < 4; j++) {
        const int px = max(v[j].x, 0);
        const int py = max(v[j].y, 0);
        int id = (px >> 1) + divk * (py >> 1);
        if (id < 0 || id >= OUTL) id = -1;  // JAX drops OOB scatter indices
        idxv[j] = id;
        if (id >= 0) {
            atomicAdd(&sTot[id], 1);
            if (!pd[j]) atomicAdd(&sVal[id], 1);
        }
    }
    __syncthreads();

    // Phase 2: block exclusive scan of the 1024 VALID counts
    const int tot = sTot[t];
    const int cnt = sVal[t];
    int inc = cnt;
#pragma unroll
    for (int o = 1; o < 32; o <<= 1) {
        int n = __shfl_up_sync(0xffffffffu, inc, o);
        if (lane >= o) inc += n;
    }
    if (lane == 31) sWarp[wid] = inc;
    __syncthreads();
    if (wid == 0) {
        const int wv = sWarp[lane];
        int winc = wv;
#pragma unroll
        for (int o = 1; o < 32; o <<= 1) {
            int n = __shfl_up_sync(0xffffffffu, winc, o);
            if (lane >= o) winc += n;
        }
        sWarp[lane] = winc - wv;            // exclusive prefix of warp sums
    }
    __syncthreads();
    const int excl = inc - cnt + sWarp[wid];

    g_cnt [b * OUTL + t] = tot;
    g_vcnt[b * OUTL + t] = cnt;
    g_off [b * OUTL + t] = excl;

    // Phase 3: reuse sVal as per-cell cursors, fill CSR list (non-padded only)
    __syncthreads();
    sVal[t] = excl;
    __syncthreads();
#pragma unroll
    for (int j = 0; j < 4; j++) {
        if (idxv[j] >= 0 && !pd[j]) {
            const int slot = atomicAdd(&sVal[idxv[j]], 1);
            g_list[b * SEQ + slot] = t + j * 1024;
        }
    }
}

// ---------------------------------------------------------------------------
// Kernel 2: gather-pool. One block per output row, one float4 per thread.
// grid = BATCH*OUTL = 16384, block = DIM4 = 288 (9 warps).
// CHUNK=4 index+row batching; __launch_bounds__(288,5) caps regs at 45 so
// occupancy stays >= 70% (the R2 lesson: occupancy IS the latency hiding).
// ---------------------------------------------------------------------------
#define CHUNK 4

__global__ __launch_bounds__(DIM4, 5)
void pool_kernel(const float4* __restrict__ hidden,
                 float4* __restrict__ out,
                 float* __restrict__ maskF,
                 unsigned char* __restrict__ maskB)
{
    const int bid = blockIdx.x;        // b*OUTL + cell
    const int b   = bid >> 10;
    const int t   = threadIdx.x;       // 0..287

    const int vcnt = g_vcnt[bid];
    const int base = g_off[bid] + b * SEQ;

    float4 acc = make_float4(0.f, 0.f, 0.f, 0.f);

    for (int i = 0; i < vcnt; i += CHUNK) {
        // Predicated batched index loads (broadcast within warp; L1-hot)
        int sv[CHUNK];
#pragma unroll
        for (int j = 0; j < CHUNK; j++)
            if (i + j < vcnt) sv[j] = __ldg(&g_list[base + i + j]);

        // Predicated row loads: up to 4 independent 16B loads in flight
        float4 hv[CHUNK];
#pragma unroll
        for (int j = 0; j < CHUNK; j++)
            if (i + j < vcnt)
                hv[j] = hidden[(size_t)((b << 12) + sv[j]) * DIM4 + t];

#pragma unroll
        for (int j = 0; j < CHUNK; j++)
            if (i + j < vcnt) {
                acc.x += hv[j].x; acc.y += hv[j].y;
                acc.z += hv[j].z; acc.w += hv[j].w;
            }
    }

    acc.x *= POOL_SCALE; acc.y *= POOL_SCALE;
    acc.z *= POOL_SCALE; acc.w *= POOL_SCALE;

    out[(size_t)bid * DIM4 + t] = acc;

    if (t == 0) {
        const bool mk = (g_cnt[bid] > 0);
        if (maskF) maskF[bid] = mk ? 1.0f : 0.0f;
        if (maskB) maskB[bid] = mk ? 1 : 0;
    }
}

// ---------------------------------------------------------------------------
extern "C" void kernel_launch(void* const* d_in, const int* in_sizes, int n_in,
                              void* d_out, int out_size)
{
    // Classify inputs by element count (robust to optional scalar output_length)
    const float*         hidden = nullptr;
    const int2*          pos    = nullptr;
    const unsigned char* pad    = nullptr;

    for (int i = 0; i < n_in; i++) {
        const long long sz = in_sizes[i];
        if (sz == (long long)BATCH * SEQ * DIM)      hidden = (const float*)d_in[i];
        else if (sz == (long long)BATCH * SEQ * 2)   pos    = (const int2*)d_in[i];
        else if (sz == (long long)BATCH * SEQ)       pad    = (const unsigned char*)d_in[i];
        // size-1 scalar (output_length) ignored — shapes are compile-time fixed
    }

    float* out = (float*)d_out;

    // Mask layout detection from out_size (elements of output dtype)
    float*         maskF = nullptr;
    unsigned char* maskB = nullptr;
    const long long extra = (long long)out_size - (long long)POOLED_ELEMS;
    if (extra == (long long)BATCH * OUTL) {
        maskF = out + POOLED_ELEMS;                       // mask as float32
    } else if (extra == (long long)BATCH * OUTL / 4) {
        maskB = (unsigned char*)(out + POOLED_ELEMS);     // mask as packed bytes
    }

    build_kernel<<<BATCH, 1024>>>(pos, pad);
    pool_kernel<<<BATCH * OUTL, DIM4>>>((const float4*)hidden,
                                        (float4*)out, maskF, maskB);
}

// round 4
// speedup vs baseline: 1.5508x; 1.0023x over previous
#include <cuda_runtime.h>
#include <cuda_bf16.h>
#include <math.h>

// Problem constants (fixed by the dataset)
#define BATCH 16
#define SEQ   4096
#define DIM   1152
#define OUTL  1024
#define DIM4  (DIM / 4)        // 288 float4 per row
#define POOLED_ELEMS ((size_t)BATCH * OUTL * DIM)   // 18,874,368

// scale = sqrt(1152) / k^2 = sqrt(1152) / 4
#define POOL_SCALE 8.4852813742385702928f

// Scratch (device globals — no allocation allowed in kernel_launch)
__device__ int g_cnt [BATCH * OUTL];   // TOTAL tokens per (batch, cell)  -> mask
__device__ int g_vcnt[BATCH * OUTL];   // NON-PADDED tokens per cell      -> loop bound
__device__ int g_off [BATCH * OUTL];   // exclusive offsets within batch
__device__ int g_list[BATCH * SEQ];    // non-padded token ids, CSR order per batch

// ---------------------------------------------------------------------------
// Kernel 1: per-batch  max_x -> divk, bucket counts (total + valid),
//           block scan, CSR fill with only non-padded tokens.
// grid = BATCH, block = 1024. Each thread handles 4 tokens (strided).
// ---------------------------------------------------------------------------
__global__ __launch_bounds__(1024, 1)
void build_kernel(const int2* __restrict__ pos,
                  const unsigned char* __restrict__ pad)
{
    __shared__ int sTot[OUTL];   // total counts (mask)
    __shared__ int sVal[OUTL];   // valid counts (scan + cursors)
    __shared__ int sWarp[32];

    const int b    = blockIdx.x;
    const int t    = threadIdx.x;
    const int lane = t & 31;
    const int wid  = t >> 5;

    const int2* p = pos + (size_t)b * SEQ;

    // Load this thread's 4 tokens' (x, y) and pad flags; track clamped max x.
    int2 v[4];
    unsigned char pd[4];
    int mymax = 0;
#pragma unroll
    for (int j = 0; j < 4; j++) {
        v[j]  = p[t + j * 1024];
        pd[j] = (pad != nullptr) ? pad[(size_t)b * SEQ + t + j * 1024] : 0;
        mymax = max(mymax, max(v[j].x, 0));
    }

    // Block max-reduce -> sWarp[0]
#pragma unroll
    for (int o = 16; o > 0; o >>= 1)
        mymax = max(mymax, __shfl_down_sync(0xffffffffu, mymax, o));
    if (lane == 0) sWarp[wid] = mymax;
    __syncthreads();
    if (wid == 0) {
        int m = sWarp[lane];
#pragma unroll
        for (int o = 16; o > 0; o >>= 1)
            m = max(m, __shfl_down_sync(0xffffffffu, m, o));
        if (lane == 0) sWarp[0] = m;
    }
    __syncthreads();
    const int divk = (sWarp[0] + 1) >> 1;   // (max_x + 1) // k, k = 2
    __syncthreads();                        // everyone has divk before sWarp reuse

    // Phase 1: bucket counts in SMEM (total for mask, valid for list)
    sTot[t] = 0;
    sVal[t] = 0;
    __syncthreads();

    int idxv[4];
#pragma unroll
    for (int j = 0; j < 4; j++) {
        const int px = max(v[j].x, 0);
        const int py = max(v[j].y, 0);
        int id = (px >> 1) + divk * (py >> 1);
        if (id < 0 || id >= OUTL) id = -1;  // JAX drops OOB scatter indices
        idxv[j] = id;
        if (id >= 0) {
            atomicAdd(&sTot[id], 1);
            if (!pd[j]) atomicAdd(&sVal[id], 1);
        }
    }
    __syncthreads();

    // Phase 2: block exclusive scan of the 1024 VALID counts
    const int tot = sTot[t];
    const int cnt = sVal[t];
    int inc = cnt;
#pragma unroll
    for (int o = 1; o < 32; o <<= 1) {
        int n = __shfl_up_sync(0xffffffffu, inc, o);
        if (lane >= o) inc += n;
    }
    if (lane == 31) sWarp[wid] = inc;
    __syncthreads();
    if (wid == 0) {
        const int wv = sWarp[lane];
        int winc = wv;
#pragma unroll
        for (int o = 1; o < 32; o <<= 1) {
            int n = __shfl_up_sync(0xffffffffu, winc, o);
            if (lane >= o) winc += n;
        }
        sWarp[lane] = winc - wv;            // exclusive prefix of warp sums
    }
    __syncthreads();
    const int excl = inc - cnt + sWarp[wid];

    g_cnt [b * OUTL + t] = tot;
    g_vcnt[b * OUTL + t] = cnt;
    g_off [b * OUTL + t] = excl;

    // Phase 3: reuse sVal as per-cell cursors, fill CSR list (non-padded only)
    __syncthreads();
    sVal[t] = excl;
    __syncthreads();
#pragma unroll
    for (int j = 0; j < 4; j++) {
        if (idxv[j] >= 0 && !pd[j]) {
            const int slot = atomicAdd(&sVal[idxv[j]], 1);
            g_list[b * SEQ + slot] = t + j * 1024;
        }
    }
}

// ---------------------------------------------------------------------------
// Kernel 2: gather-pool. One block per output row, one float4 per thread.
// grid = BATCH*OUTL = 16384, block = DIM4 = 288 (9 warps).
// CHUNK=4 index+row batching; __launch_bounds__(288,5) caps regs at 45 so
// occupancy stays >= 70% (the R2 lesson: occupancy IS the latency hiding).
// ---------------------------------------------------------------------------
#define CHUNK 4

__global__ __launch_bounds__(DIM4, 5)
void pool_kernel(const float4* __restrict__ hidden,
                 float4* __restrict__ out,
                 float* __restrict__ maskF,
                 unsigned char* __restrict__ maskB)
{
    const int bid = blockIdx.x;        // b*OUTL + cell
    const int b   = bid >> 10;
    const int t   = threadIdx.x;       // 0..287

    const int vcnt = g_vcnt[bid];
    const int base = g_off[bid] + b * SEQ;

    float4 acc = make_float4(0.f, 0.f, 0.f, 0.f);

    for (int i = 0; i < vcnt; i += CHUNK) {
        // Predicated batched index loads (broadcast within warp; L1-hot)
        int sv[CHUNK];
#pragma unroll
        for (int j = 0; j < CHUNK; j++)
            if (i + j < vcnt) sv[j] = __ldg(&g_list[base + i + j]);

        // Predicated row loads: up to 4 independent 16B loads in flight
        float4 hv[CHUNK];
#pragma unroll
        for (int j = 0; j < CHUNK; j++)
            if (i + j < vcnt)
                hv[j] = hidden[(size_t)((b << 12) + sv[j]) * DIM4 + t];

#pragma unroll
        for (int j = 0; j < CHUNK; j++)
            if (i + j < vcnt) {
                acc.x += hv[j].x; acc.y += hv[j].y;
                acc.z += hv[j].z; acc.w += hv[j].w;
            }
    }

    acc.x *= POOL_SCALE; acc.y *= POOL_SCALE;
    acc.z *= POOL_SCALE; acc.w *= POOL_SCALE;

    out[(size_t)bid * DIM4 + t] = acc;

    if (t == 0) {
        const bool mk = (g_cnt[bid] > 0);
        if (maskF) maskF[bid] = mk ? 1.0f : 0.0f;
        if (maskB) maskB[bid] = mk ? 1 : 0;
    }
}

// ---------------------------------------------------------------------------
extern "C" void kernel_launch(void* const* d_in, const int* in_sizes, int n_in,
                              void* d_out, int out_size)
{
    // Classify inputs by element count (robust to optional scalar output_length)
    const float*         hidden = nullptr;
    const int2*          pos    = nullptr;
    const unsigned char* pad    = nullptr;

    for (int i = 0; i < n_in; i++) {
        const long long sz = in_sizes[i];
        if (sz == (long long)BATCH * SEQ * DIM)      hidden = (const float*)d_in[i];
        else if (sz == (long long)BATCH * SEQ * 2)   pos    = (const int2*)d_in[i];
        else if (sz == (long long)BATCH * SEQ)       pad    = (const unsigned char*)d_in[i];
        // size-1 scalar (output_length) ignored — shapes are compile-time fixed
    }

    float* out = (float*)d_out;

    // Mask layout detection from out_size (elements of output dtype)
    float*         maskF = nullptr;
    unsigned char* maskB = nullptr;
    const long long extra = (long long)out_size - (long long)POOLED_ELEMS;
    if (extra == (long long)BATCH * OUTL) {
        maskF = out + POOLED_ELEMS;                       // mask as float32
    } else if (extra == (long long)BATCH * OUTL / 4) {
        maskB = (unsigned char*)(out + POOLED_ELEMS);     // mask as packed bytes
    }

    build_kernel<<<BATCH, 1024>>>(pos, pad);
    pool_kernel<<<BATCH * OUTL, DIM4>>>((const float4*)hidden,
                                        (float4*)out, maskF, maskB);
}